// round 5
// baseline (speedup 1.0000x reference)
#include <cuda_runtime.h>

#define BN 2
#define NN 512
#define TT 24
#define HH 8
#define DD 8
#define EE 64
#define SCALE 0.125f
#define LOG2E 1.44269504088896340736f

typedef unsigned long long u64;

// Intermediate per-head attention output (b, n, t, e) before output projection.
__device__ float g_mid[BN * NN * TT * EE];

__device__ __forceinline__ float fast_exp2(float x) {
    float y;
    asm("ex2.approx.f32 %0, %1;" : "=f"(y) : "f"(x));
    return y;
}
__device__ __forceinline__ u64 pack2(float a, float b) {
    u64 r; asm("mov.b64 %0, {%1, %2};" : "=l"(r) : "f"(a), "f"(b)); return r;
}
__device__ __forceinline__ void unpack2(u64 v, float& a, float& b) {
    asm("mov.b64 {%0, %1}, %2;" : "=f"(a), "=f"(b) : "l"(v));
}
__device__ __forceinline__ u64 fma2(u64 a, u64 b, u64 c) {
    u64 d; asm("fma.rn.f32x2 %0, %1, %2, %3;" : "=l"(d) : "l"(a), "l"(b), "l"(c)); return d;
}
__device__ __forceinline__ u64 add2(u64 a, u64 b) {
    u64 d; asm("add.rn.f32x2 %0, %1, %2;" : "=l"(d) : "l"(a), "l"(b)); return d;
}

// One CTA per (b, t, h, half): 256 threads, 1 query per thread. grid = 768.
// occ=4 -> 32 warps/SM; reg cap 64 fits the 1-query working set without spill.
__global__ __launch_bounds__(256, 4) void attn_kernel(
    const float* __restrict__ Vg, const float* __restrict__ Kg, const float* __restrict__ Qg,
    const float* __restrict__ Wv, const float* __restrict__ Wk, const float* __restrict__ Wq)
{
    __shared__ float sKT[DD * NN];   // sKT[j*NN + k]
    __shared__ float sVT[DD * NN];   // sVT[j*NN + k]
    __shared__ float sWk[DD * DD], sWv[DD * DD], sWq[DD * DD];

    const int tid = threadIdx.x;
    const int gid  = blockIdx.x >> 1;
    const int half = blockIdx.x & 1;
    const int h = gid & (HH - 1);
    const int t = (gid >> 3) % TT;
    const int b = gid / (HH * TT);

    if (tid < DD * DD) {
        sWv[tid] = Wv[tid];
        sWk[tid] = Wk[tid];
        sWq[tid] = Wq[tid];
    }
    __syncthreads();

    const size_t base = ((size_t)b * NN * TT + t) * EE + (size_t)h * DD;
    const int rowstride = TT * EE;  // 1536 floats between nodes

    // ---- Project K and V (both transposed) for all 512 nodes ----
    for (int r = tid; r < NN; r += 256) {
        const float4* kp = (const float4*)(Kg + base + (size_t)r * rowstride);
        const float4* vp = (const float4*)(Vg + base + (size_t)r * rowstride);
        float4 ka = kp[0], kb = kp[1];
        float4 va = vp[0], vb = vp[1];
        float kr[8] = {ka.x, ka.y, ka.z, ka.w, kb.x, kb.y, kb.z, kb.w};
        float vr[8] = {va.x, va.y, va.z, va.w, vb.x, vb.y, vb.z, vb.w};
        #pragma unroll
        for (int i = 0; i < DD; i++) {
            float sk = 0.f, sv = 0.f;
            #pragma unroll
            for (int j = 0; j < DD; j++) {
                sk = fmaf(kr[j], sWk[i * DD + j], sk);
                sv = fmaf(vr[j], sWv[i * DD + j], sv);
            }
            sKT[i * NN + r] = sk;    // consecutive lanes -> consecutive banks
            sVT[i * NN + r] = sv;
        }
    }

    // ---- Project this thread's query; fold scale*log2e; pack dup ----
    const int q = half * 256 + tid;
    u64 qp[8];
    {
        const float4* qptr = (const float4*)(Qg + base + (size_t)q * rowstride);
        float4 qa = qptr[0], qb = qptr[1];
        float qr[8] = {qa.x, qa.y, qa.z, qa.w, qb.x, qb.y, qb.z, qb.w};
        #pragma unroll
        for (int i = 0; i < DD; i++) {
            float s = 0.f;
            #pragma unroll
            for (int j = 0; j < DD; j++) s = fmaf(qr[j], sWq[i * DD + j], s);
            s *= (SCALE * LOG2E);
            qp[i] = pack2(s, s);
        }
    }
    __syncthreads();

    // ---- Main loop: 4 keys / iter, packed f32x2; SMEM reads are broadcasts ----
    u64 acc[8];
    #pragma unroll
    for (int j = 0; j < 8; j++) acc[j] = 0;
    u64 lp = 0;

    #pragma unroll 1
    for (int k = 0; k < NN; k += 4) {
        u64 s01 = 0, s23 = 0;
        #pragma unroll
        for (int j = 0; j < DD; j++) {
            ulonglong2 kv = *(const ulonglong2*)(sKT + j * NN + k);  // 4 keys @ dim j
            s01 = fma2(kv.x, qp[j], s01);
            s23 = fma2(kv.y, qp[j], s23);
        }
        float a0, a1, a2, a3;
        unpack2(s01, a0, a1); unpack2(s23, a2, a3);
        u64 p01 = pack2(fast_exp2(a0), fast_exp2(a1));
        u64 p23 = pack2(fast_exp2(a2), fast_exp2(a3));
        lp = add2(lp, p01);
        lp = add2(lp, p23);

        #pragma unroll
        for (int j = 0; j < DD; j++) {
            ulonglong2 vv = *(const ulonglong2*)(sVT + j * NN + k);  // 4 keys @ dim j
            acc[j] = fma2(p01, vv.x, acc[j]);
            acc[j] = fma2(p23, vv.y, acc[j]);
        }
    }

    // ---- Epilogue: fold packed halves, normalize, store ----
    float l0, l1;
    unpack2(lp, l0, l1);
    const float inv = 1.0f / (l0 + l1);
    float o[8];
    #pragma unroll
    for (int j = 0; j < 8; j++) {
        float x, y;
        unpack2(acc[j], x, y);
        o[j] = (x + y) * inv;
    }
    float* op = g_mid + base + (size_t)q * rowstride;
    ((float4*)op)[0] = make_float4(o[0], o[1], o[2], o[3]);
    ((float4*)op)[1] = make_float4(o[4], o[5], o[6], o[7]);
}

// Output projection: y[r,:] = x[r,:] @ Wo^T + bo, R = B*N*T = 24576 rows.
// 256 threads, 32 rows/CTA (grid 768). warp -> 8 output cols (W broadcasts);
// lane -> row. x staged with stride-65 pad -> conflict-free scalar LDS.
#define RPB 32
#define XS 65      // bank = (r + j) mod 32 -> conflict-free scalar x reads
#define WS 68      // padded W^T row stride (16B-aligned quads at i0 mult of 8)

__global__ __launch_bounds__(256) void proj_kernel(
    const float* __restrict__ Wo, const float* __restrict__ bo, float* __restrict__ out)
{
    __shared__ float sWT[EE * WS];   // sWT[j*WS + i] = Wo[i*EE + j]
    __shared__ float sb[EE];
    __shared__ float sx[RPB * XS];

    const int tid = threadIdx.x;
    for (int idx = tid; idx < EE * EE; idx += 256) {
        int i = idx >> 6, j = idx & 63;
        sWT[j * WS + i] = Wo[idx];
    }
    if (tid < EE) sb[tid] = bo[tid];

    const size_t rbase = (size_t)blockIdx.x * RPB * EE;
    for (int idx = tid; idx < RPB * EE; idx += 256)
        sx[(idx >> 6) * XS + (idx & 63)] = g_mid[rbase + idx];
    __syncthreads();

    const int w = tid >> 5;       // warp -> 8 output columns
    const int lane = tid & 31;    // lane -> row
    const int i0 = w * 8;

    u64 a01 = pack2(sb[i0 + 0], sb[i0 + 1]);
    u64 a23 = pack2(sb[i0 + 2], sb[i0 + 3]);
    u64 a45 = pack2(sb[i0 + 4], sb[i0 + 5]);
    u64 a67 = pack2(sb[i0 + 6], sb[i0 + 7]);

    const float* xr = sx + lane * XS;
    #pragma unroll 8
    for (int j = 0; j < EE; j++) {
        float xj = xr[j];                    // conflict-free (stride 65)
        u64 xp = pack2(xj, xj);
        const ulonglong2* wp = (const ulonglong2*)(sWT + j * WS + i0);  // broadcast
        ulonglong2 wa = wp[0];
        ulonglong2 wb = wp[1];
        a01 = fma2(xp, wa.x, a01);
        a23 = fma2(xp, wa.y, a23);
        a45 = fma2(xp, wb.x, a45);
        a67 = fma2(xp, wb.y, a67);
    }

    float* orow = out + rbase + (size_t)lane * EE + i0;
    ulonglong2 oa; oa.x = a01; oa.y = a23;
    ulonglong2 ob; ob.x = a45; ob.y = a67;
    ((ulonglong2*)orow)[0] = oa;
    ((ulonglong2*)orow)[1] = ob;
}

extern "C" void kernel_launch(void* const* d_in, const int* in_sizes, int n_in,
                              void* d_out, int out_size)
{
    const float* values = (const float*)d_in[0];
    const float* keys   = (const float*)d_in[1];
    const float* query  = (const float*)d_in[2];
    const float* Wv     = (const float*)d_in[3];
    const float* Wk     = (const float*)d_in[4];
    const float* Wq     = (const float*)d_in[5];
    const float* Wo     = (const float*)d_in[6];
    const float* bo     = (const float*)d_in[7];

    attn_kernel<<<BN * TT * HH * 2, 256>>>(values, keys, query, Wv, Wk, Wq);
    proj_kernel<<<BN * NN * TT / RPB, 256>>>(Wo, bo, (float*)d_out);
}

// round 6
// speedup vs baseline: 1.3665x; 1.3665x over previous
#include <cuda_runtime.h>

#define BN 2
#define NN 512
#define TT 24
#define HH 8
#define DD 8
#define EE 64
#define SCALE 0.125f
#define LOG2E 1.44269504088896340736f

typedef unsigned long long u64;

// Intermediate per-head attention output (b, n, t, e) before output projection.
__device__ float g_mid[BN * NN * TT * EE];

__device__ __forceinline__ float fast_exp2(float x) {
    float y;
    asm("ex2.approx.f32 %0, %1;" : "=f"(y) : "f"(x));
    return y;
}
__device__ __forceinline__ u64 pack2(float a, float b) {
    u64 r; asm("mov.b64 %0, {%1, %2};" : "=l"(r) : "f"(a), "f"(b)); return r;
}
__device__ __forceinline__ void unpack2(u64 v, float& a, float& b) {
    asm("mov.b64 {%0, %1}, %2;" : "=f"(a), "=f"(b) : "l"(v));
}
__device__ __forceinline__ u64 fma2(u64 a, u64 b, u64 c) {
    u64 d; asm("fma.rn.f32x2 %0, %1, %2, %3;" : "=l"(d) : "l"(a), "l"(b), "l"(c)); return d;
}
__device__ __forceinline__ u64 add2(u64 a, u64 b) {
    u64 d; asm("add.rn.f32x2 %0, %1, %2;" : "=l"(d) : "l"(a), "l"(b)); return d;
}

// One CTA per (b, t, h) group: 256 threads, 2 queries per thread. grid = 384.
// (R3 configuration: measured at the fp32 fma-pipe floor, ~86us.)
__global__ __launch_bounds__(256, 2) void attn_kernel(
    const float* __restrict__ Vg, const float* __restrict__ Kg, const float* __restrict__ Qg,
    const float* __restrict__ Wv, const float* __restrict__ Wk, const float* __restrict__ Wq)
{
    __shared__ float sKT[DD * NN];   // sKT[j*NN + k]
    __shared__ float sVT[DD * NN];   // sVT[j*NN + k]
    __shared__ float sWk[DD * DD], sWv[DD * DD], sWq[DD * DD];

    const int tid = threadIdx.x;
    const int gid = blockIdx.x;
    const int h = gid & (HH - 1);
    const int t = (gid >> 3) % TT;
    const int b = gid / (HH * TT);

    if (tid < DD * DD) {
        sWv[tid] = Wv[tid];
        sWk[tid] = Wk[tid];
        sWq[tid] = Wq[tid];
    }
    __syncthreads();

    const size_t base = ((size_t)b * NN * TT + t) * EE + (size_t)h * DD;
    const int rowstride = TT * EE;  // 1536 floats between nodes

    // ---- Project K and V (both transposed) for all 512 nodes ----
    for (int r = tid; r < NN; r += 256) {
        const float4* kp = (const float4*)(Kg + base + (size_t)r * rowstride);
        const float4* vp = (const float4*)(Vg + base + (size_t)r * rowstride);
        float4 ka = kp[0], kb = kp[1];
        float4 va = vp[0], vb = vp[1];
        float kr[8] = {ka.x, ka.y, ka.z, ka.w, kb.x, kb.y, kb.z, kb.w};
        float vr[8] = {va.x, va.y, va.z, va.w, vb.x, vb.y, vb.z, vb.w};
        #pragma unroll
        for (int i = 0; i < DD; i++) {
            float sk = 0.f, sv = 0.f;
            #pragma unroll
            for (int j = 0; j < DD; j++) {
                sk = fmaf(kr[j], sWk[i * DD + j], sk);
                sv = fmaf(vr[j], sWv[i * DD + j], sv);
            }
            sKT[i * NN + r] = sk;    // consecutive lanes -> consecutive banks
            sVT[i * NN + r] = sv;
        }
    }

    // ---- Project both queries of this thread; fold scale*log2e; pack dup ----
    u64 qpA[8], qpB[8];
    #pragma unroll
    for (int sel = 0; sel < 2; sel++) {
        const int q = tid + sel * 256;
        const float4* qptr = (const float4*)(Qg + base + (size_t)q * rowstride);
        float4 qa = qptr[0], qb = qptr[1];
        float qr[8] = {qa.x, qa.y, qa.z, qa.w, qb.x, qb.y, qb.z, qb.w};
        #pragma unroll
        for (int i = 0; i < DD; i++) {
            float s = 0.f;
            #pragma unroll
            for (int j = 0; j < DD; j++) s = fmaf(qr[j], sWq[i * DD + j], s);
            s *= (SCALE * LOG2E);
            if (sel == 0) qpA[i] = pack2(s, s); else qpB[i] = pack2(s, s);
        }
    }
    __syncthreads();

    // ---- Main loop: 4 keys / iter, 2 queries / thread, packed f32x2.
    //      All SMEM reads are LDS.128 warp broadcasts shared by both queries.
    u64 accA[8], accB[8];
    #pragma unroll
    for (int j = 0; j < 8; j++) { accA[j] = 0; accB[j] = 0; }
    u64 lpA = 0, lpB = 0;

    #pragma unroll 2
    for (int k = 0; k < NN; k += 4) {
        u64 sA01 = 0, sA23 = 0, sB01 = 0, sB23 = 0;
        #pragma unroll
        for (int j = 0; j < DD; j++) {
            ulonglong2 kv = *(const ulonglong2*)(sKT + j * NN + k);  // 4 keys @ dim j
            sA01 = fma2(kv.x, qpA[j], sA01);
            sA23 = fma2(kv.y, qpA[j], sA23);
            sB01 = fma2(kv.x, qpB[j], sB01);
            sB23 = fma2(kv.y, qpB[j], sB23);
        }
        float a0, a1, a2, a3, b0, b1, b2, b3;
        unpack2(sA01, a0, a1); unpack2(sA23, a2, a3);
        unpack2(sB01, b0, b1); unpack2(sB23, b2, b3);
        u64 pA01 = pack2(fast_exp2(a0), fast_exp2(a1));
        u64 pA23 = pack2(fast_exp2(a2), fast_exp2(a3));
        u64 pB01 = pack2(fast_exp2(b0), fast_exp2(b1));
        u64 pB23 = pack2(fast_exp2(b2), fast_exp2(b3));
        lpA = add2(lpA, pA01); lpA = add2(lpA, pA23);
        lpB = add2(lpB, pB01); lpB = add2(lpB, pB23);

        #pragma unroll
        for (int j = 0; j < DD; j++) {
            ulonglong2 vv = *(const ulonglong2*)(sVT + j * NN + k);  // 4 keys @ dim j
            accA[j] = fma2(pA01, vv.x, accA[j]);
            accA[j] = fma2(pA23, vv.y, accA[j]);
            accB[j] = fma2(pB01, vv.x, accB[j]);
            accB[j] = fma2(pB23, vv.y, accB[j]);
        }
    }

    // ---- Epilogue: fold packed halves, normalize, store both query rows ----
    #pragma unroll
    for (int sel = 0; sel < 2; sel++) {
        const u64* acc = sel ? accB : accA;
        u64 lp = sel ? lpB : lpA;
        float l0, l1;
        unpack2(lp, l0, l1);
        const float inv = 1.0f / (l0 + l1);
        float o[8];
        #pragma unroll
        for (int j = 0; j < 8; j++) {
            float x, y;
            unpack2(acc[j], x, y);
            o[j] = (x + y) * inv;
        }
        float* op = g_mid + base + (size_t)(tid + sel * 256) * rowstride;
        ((float4*)op)[0] = make_float4(o[0], o[1], o[2], o[3]);
        ((float4*)op)[1] = make_float4(o[4], o[5], o[6], o[7]);
    }
}

// Output projection: y[r,:] = x[r,:] @ Wo^T + bo, R = B*N*T = 24576 rows.
// 128 rows/CTA (grid 192, occ 4 -> single wave). warp -> 8 output cols:
// W reads are LDS.128 broadcasts shared by 4 rows/thread; x reads are
// conflict-free scalar LDS (stride-65 pad). Inner loop is fma2-bound.
#define PRPB 128
#define PXS 65     // x row stride: bank = (lane + j) mod 32 -> conflict-free
#define PWS 68     // W^T row stride: 272B, 16B-aligned quads at col mult of 4

__global__ __launch_bounds__(256) void proj_kernel(
    const float* __restrict__ Wo, const float* __restrict__ bo, float* __restrict__ out)
{
    __shared__ float sWT[EE * PWS];    // sWT[j*PWS + i] = Wo[i*EE + j]
    __shared__ float sb[EE];
    __shared__ float sx[PRPB * PXS];

    const int tid = threadIdx.x;
    for (int idx = tid; idx < EE * EE; idx += 256) {
        int i = idx >> 6, j = idx & 63;
        sWT[j * PWS + i] = Wo[idx];
    }
    if (tid < EE) sb[tid] = bo[tid];

    const size_t rbase = (size_t)blockIdx.x * PRPB * EE;
    // Stage x: 8192 floats via float4 (32 per thread), scatter to padded rows.
    for (int idx = tid * 4; idx < PRPB * EE; idx += 256 * 4) {
        float4 v = *(const float4*)(g_mid + rbase + idx);
        float* dst = sx + (idx >> 6) * PXS + (idx & 63);
        dst[0] = v.x; dst[1] = v.y; dst[2] = v.z; dst[3] = v.w;
    }
    __syncthreads();

    const int w = tid >> 5;       // warp -> 8 output columns
    const int lane = tid & 31;    // lane -> rows lane, lane+32, lane+64, lane+96
    const int i0 = w * 8;

    u64 acc[4][4];
    {
        u64 b01 = pack2(sb[i0 + 0], sb[i0 + 1]);
        u64 b23 = pack2(sb[i0 + 2], sb[i0 + 3]);
        u64 b45 = pack2(sb[i0 + 4], sb[i0 + 5]);
        u64 b67 = pack2(sb[i0 + 6], sb[i0 + 7]);
        #pragma unroll
        for (int r = 0; r < 4; r++) {
            acc[r][0] = b01; acc[r][1] = b23; acc[r][2] = b45; acc[r][3] = b67;
        }
    }

    const float* xr0 = sx + lane * PXS;
    #pragma unroll 4
    for (int j = 0; j < EE; j++) {
        const ulonglong2* wp = (const ulonglong2*)(sWT + j * PWS + i0);  // broadcast
        ulonglong2 wa = wp[0];   // cols i0..i0+3
        ulonglong2 wb = wp[1];   // cols i0+4..i0+7
        #pragma unroll
        for (int r = 0; r < 4; r++) {
            float xj = xr0[r * 32 * PXS + j];   // conflict-free scalar LDS
            u64 xp = pack2(xj, xj);
            acc[r][0] = fma2(xp, wa.x, acc[r][0]);
            acc[r][1] = fma2(xp, wa.y, acc[r][1]);
            acc[r][2] = fma2(xp, wb.x, acc[r][2]);
            acc[r][3] = fma2(xp, wb.y, acc[r][3]);
        }
    }

    #pragma unroll
    for (int r = 0; r < 4; r++) {
        float* orow = out + rbase + (size_t)(lane + r * 32) * EE + i0;
        ulonglong2 oa; oa.x = acc[r][0]; oa.y = acc[r][1];
        ulonglong2 ob; ob.x = acc[r][2]; ob.y = acc[r][3];
        ((ulonglong2*)orow)[0] = oa;
        ((ulonglong2*)orow)[1] = ob;
    }
}

extern "C" void kernel_launch(void* const* d_in, const int* in_sizes, int n_in,
                              void* d_out, int out_size)
{
    const float* values = (const float*)d_in[0];
    const float* keys   = (const float*)d_in[1];
    const float* query  = (const float*)d_in[2];
    const float* Wv     = (const float*)d_in[3];
    const float* Wk     = (const float*)d_in[4];
    const float* Wq     = (const float*)d_in[5];
    const float* Wo     = (const float*)d_in[6];
    const float* bo     = (const float*)d_in[7];

    attn_kernel<<<BN * TT * HH, 256>>>(values, keys, query, Wv, Wk, Wq);
    proj_kernel<<<BN * NN * TT / PRPB, 256>>>(Wo, bo, (float*)d_out);
}

// round 7
// speedup vs baseline: 1.4082x; 1.0305x over previous
#include <cuda_runtime.h>

#define BN 2
#define NN 512
#define TT 24
#define HH 8
#define DD 8
#define EE 64
#define SCALE 0.125f
#define LOG2E 1.44269504088896340736f

typedef unsigned long long u64;

// Intermediate per-head attention output (b, n, t, e) before output projection.
__device__ float g_mid[BN * NN * TT * EE];

__device__ __forceinline__ float fast_exp2(float x) {
    float y;
    asm("ex2.approx.f32 %0, %1;" : "=f"(y) : "f"(x));
    return y;
}
__device__ __forceinline__ u64 pack2(float a, float b) {
    u64 r; asm("mov.b64 %0, {%1, %2};" : "=l"(r) : "f"(a), "f"(b)); return r;
}
__device__ __forceinline__ void unpack2(u64 v, float& a, float& b) {
    asm("mov.b64 {%0, %1}, %2;" : "=f"(a), "=f"(b) : "l"(v));
}
__device__ __forceinline__ u64 fma2(u64 a, u64 b, u64 c) {
    u64 d; asm("fma.rn.f32x2 %0, %1, %2, %3;" : "=l"(d) : "l"(a), "l"(b), "l"(c)); return d;
}
__device__ __forceinline__ u64 add2(u64 a, u64 b) {
    u64 d; asm("add.rn.f32x2 %0, %1, %2;" : "=l"(d) : "l"(a), "l"(b)); return d;
}

// One CTA per (b, t, h) group: 256 threads, 2 queries per thread. grid = 384.
// (R3 configuration: measured ~87us; protected.)
__global__ __launch_bounds__(256, 2) void attn_kernel(
    const float* __restrict__ Vg, const float* __restrict__ Kg, const float* __restrict__ Qg,
    const float* __restrict__ Wv, const float* __restrict__ Wk, const float* __restrict__ Wq)
{
    __shared__ float sKT[DD * NN];   // sKT[j*NN + k]
    __shared__ float sVT[DD * NN];   // sVT[j*NN + k]
    __shared__ float sWk[DD * DD], sWv[DD * DD], sWq[DD * DD];

    const int tid = threadIdx.x;
    const int gid = blockIdx.x;
    const int h = gid & (HH - 1);
    const int t = (gid >> 3) % TT;
    const int b = gid / (HH * TT);

    if (tid < DD * DD) {
        sWv[tid] = Wv[tid];
        sWk[tid] = Wk[tid];
        sWq[tid] = Wq[tid];
    }
    __syncthreads();

    const size_t base = ((size_t)b * NN * TT + t) * EE + (size_t)h * DD;
    const int rowstride = TT * EE;  // 1536 floats between nodes

    // ---- Project K and V (both transposed) for all 512 nodes ----
    for (int r = tid; r < NN; r += 256) {
        const float4* kp = (const float4*)(Kg + base + (size_t)r * rowstride);
        const float4* vp = (const float4*)(Vg + base + (size_t)r * rowstride);
        float4 ka = kp[0], kb = kp[1];
        float4 va = vp[0], vb = vp[1];
        float kr[8] = {ka.x, ka.y, ka.z, ka.w, kb.x, kb.y, kb.z, kb.w};
        float vr[8] = {va.x, va.y, va.z, va.w, vb.x, vb.y, vb.z, vb.w};
        #pragma unroll
        for (int i = 0; i < DD; i++) {
            float sk = 0.f, sv = 0.f;
            #pragma unroll
            for (int j = 0; j < DD; j++) {
                sk = fmaf(kr[j], sWk[i * DD + j], sk);
                sv = fmaf(vr[j], sWv[i * DD + j], sv);
            }
            sKT[i * NN + r] = sk;    // consecutive lanes -> consecutive banks
            sVT[i * NN + r] = sv;
        }
    }

    // ---- Project both queries of this thread; fold scale*log2e; pack dup ----
    u64 qpA[8], qpB[8];
    #pragma unroll
    for (int sel = 0; sel < 2; sel++) {
        const int q = tid + sel * 256;
        const float4* qptr = (const float4*)(Qg + base + (size_t)q * rowstride);
        float4 qa = qptr[0], qb = qptr[1];
        float qr[8] = {qa.x, qa.y, qa.z, qa.w, qb.x, qb.y, qb.z, qb.w};
        #pragma unroll
        for (int i = 0; i < DD; i++) {
            float s = 0.f;
            #pragma unroll
            for (int j = 0; j < DD; j++) s = fmaf(qr[j], sWq[i * DD + j], s);
            s *= (SCALE * LOG2E);
            if (sel == 0) qpA[i] = pack2(s, s); else qpB[i] = pack2(s, s);
        }
    }
    __syncthreads();

    // ---- Main loop: 4 keys / iter, 2 queries / thread, packed f32x2.
    //      All SMEM reads are LDS.128 warp broadcasts shared by both queries.
    u64 accA[8], accB[8];
    #pragma unroll
    for (int j = 0; j < 8; j++) { accA[j] = 0; accB[j] = 0; }
    u64 lpA = 0, lpB = 0;

    #pragma unroll 2
    for (int k = 0; k < NN; k += 4) {
        u64 sA01 = 0, sA23 = 0, sB01 = 0, sB23 = 0;
        #pragma unroll
        for (int j = 0; j < DD; j++) {
            ulonglong2 kv = *(const ulonglong2*)(sKT + j * NN + k);  // 4 keys @ dim j
            sA01 = fma2(kv.x, qpA[j], sA01);
            sA23 = fma2(kv.y, qpA[j], sA23);
            sB01 = fma2(kv.x, qpB[j], sB01);
            sB23 = fma2(kv.y, qpB[j], sB23);
        }
        float a0, a1, a2, a3, b0, b1, b2, b3;
        unpack2(sA01, a0, a1); unpack2(sA23, a2, a3);
        unpack2(sB01, b0, b1); unpack2(sB23, b2, b3);
        u64 pA01 = pack2(fast_exp2(a0), fast_exp2(a1));
        u64 pA23 = pack2(fast_exp2(a2), fast_exp2(a3));
        u64 pB01 = pack2(fast_exp2(b0), fast_exp2(b1));
        u64 pB23 = pack2(fast_exp2(b2), fast_exp2(b3));
        lpA = add2(lpA, pA01); lpA = add2(lpA, pA23);
        lpB = add2(lpB, pB01); lpB = add2(lpB, pB23);

        #pragma unroll
        for (int j = 0; j < DD; j++) {
            ulonglong2 vv = *(const ulonglong2*)(sVT + j * NN + k);  // 4 keys @ dim j
            accA[j] = fma2(pA01, vv.x, accA[j]);
            accA[j] = fma2(pA23, vv.y, accA[j]);
            accB[j] = fma2(pB01, vv.x, accB[j]);
            accB[j] = fma2(pB23, vv.y, accB[j]);
        }
    }

    // ---- Epilogue: fold packed halves, normalize, store both query rows ----
    #pragma unroll
    for (int sel = 0; sel < 2; sel++) {
        const u64* acc = sel ? accB : accA;
        u64 lp = sel ? lpB : lpA;
        float l0, l1;
        unpack2(lp, l0, l1);
        const float inv = 1.0f / (l0 + l1);
        float o[8];
        #pragma unroll
        for (int j = 0; j < 8; j++) {
            float x, y;
            unpack2(acc[j], x, y);
            o[j] = (x + y) * inv;
        }
        float* op = g_mid + base + (size_t)(tid + sel * 256) * rowstride;
        ((float4*)op)[0] = make_float4(o[0], o[1], o[2], o[3]);
        ((float4*)op)[1] = make_float4(o[4], o[5], o[6], o[7]);
    }
}

// Output projection: y[r,:] = x[r,:] @ Wo^T + bo, R = B*N*T = 24576 rows.
// 64 rows/CTA (grid 384 -> single wave, ~2.6 CTAs/SM at occ 6).
// warp -> 8 output cols (W LDS.128 broadcasts shared by 2 rows/thread);
// x loaded as float4 per 4 j. Inner loop fma2-bound (LDS issue ~40cyc < fma 64cyc
// per 4 j). Results bounced through SMEM for fully coalesced STG.128.
#define PRPB 64
#define PXS 68     // x row stride (floats): float4-aligned
#define PWS 68     // W^T row stride: 16B-aligned quads at col mult of 4

__global__ __launch_bounds__(256) void proj_kernel(
    const float* __restrict__ Wo, const float* __restrict__ bo, float* __restrict__ out)
{
    __shared__ float sWT[EE * PWS];    // sWT[j*PWS + i] = Wo[i*EE + j]  (17.4 KB)
    __shared__ float sb[EE];
    __shared__ float sx[PRPB * PXS];   // 17.4 KB

    const int tid = threadIdx.x;
    for (int idx = tid; idx < EE * EE; idx += 256) {
        int i = idx >> 6, j = idx & 63;
        sWT[j * PWS + i] = Wo[idx];
    }
    if (tid < EE) sb[tid] = bo[tid];

    const size_t rbase = (size_t)blockIdx.x * PRPB * EE;
    // Stage x: 4096 floats, coalesced float4 reads, padded-row writes.
    #pragma unroll
    for (int idx = tid * 4; idx < PRPB * EE; idx += 256 * 4) {
        float4 v = *(const float4*)(g_mid + rbase + idx);
        float* dst = sx + (idx >> 6) * PXS + (idx & 63);
        dst[0] = v.x; dst[1] = v.y; dst[2] = v.z; dst[3] = v.w;
    }
    __syncthreads();

    const int w = tid >> 5;       // warp -> 8 output columns
    const int lane = tid & 31;    // lane -> rows lane, lane+32
    const int i0 = w * 8;

    u64 aA[4], aB[4];
    {
        u64 b01 = pack2(sb[i0 + 0], sb[i0 + 1]);
        u64 b23 = pack2(sb[i0 + 2], sb[i0 + 3]);
        u64 b45 = pack2(sb[i0 + 4], sb[i0 + 5]);
        u64 b67 = pack2(sb[i0 + 6], sb[i0 + 7]);
        aA[0] = b01; aA[1] = b23; aA[2] = b45; aA[3] = b67;
        aB[0] = b01; aB[1] = b23; aB[2] = b45; aB[3] = b67;
    }

    const float* xA = sx + lane * PXS;
    const float* xB = sx + (lane + 32) * PXS;
    #pragma unroll 4
    for (int j4 = 0; j4 < EE; j4 += 4) {
        float4 xa4 = *(const float4*)(xA + j4);   // 4-way conflict, amortized
        float4 xb4 = *(const float4*)(xB + j4);
        const float xa[4] = {xa4.x, xa4.y, xa4.z, xa4.w};
        const float xb[4] = {xb4.x, xb4.y, xb4.z, xb4.w};
        #pragma unroll
        for (int jj = 0; jj < 4; jj++) {
            const ulonglong2* wp = (const ulonglong2*)(sWT + (j4 + jj) * PWS + i0);  // broadcast
            ulonglong2 wa = wp[0];
            ulonglong2 wb = wp[1];
            u64 xpa = pack2(xa[jj], xa[jj]);
            u64 xpb = pack2(xb[jj], xb[jj]);
            aA[0] = fma2(xpa, wa.x, aA[0]);
            aA[1] = fma2(xpa, wa.y, aA[1]);
            aA[2] = fma2(xpa, wb.x, aA[2]);
            aA[3] = fma2(xpa, wb.y, aA[3]);
            aB[0] = fma2(xpb, wa.x, aB[0]);
            aB[1] = fma2(xpb, wa.y, aB[1]);
            aB[2] = fma2(xpb, wb.x, aB[2]);
            aB[3] = fma2(xpb, wb.y, aB[3]);
        }
    }

    // ---- Bounce results through SMEM so global stores are coalesced ----
    __syncthreads();   // done reading sx as input
    #pragma unroll
    for (int r = 0; r < 2; r++) {
        const u64* a = r ? aB : aA;
        float* dst = sx + (lane + r * 32) * PXS + i0;
        #pragma unroll
        for (int c = 0; c < 4; c++) {
            float lo, hi;
            unpack2(a[c], lo, hi);
            dst[2 * c] = lo;
            dst[2 * c + 1] = hi;
        }
    }
    __syncthreads();
    #pragma unroll
    for (int idx = tid * 4; idx < PRPB * EE; idx += 256 * 4) {
        const float* src = sx + (idx >> 6) * PXS + (idx & 63);
        *(float4*)(out + rbase + idx) = make_float4(src[0], src[1], src[2], src[3]);
    }
}

extern "C" void kernel_launch(void* const* d_in, const int* in_sizes, int n_in,
                              void* d_out, int out_size)
{
    const float* values = (const float*)d_in[0];
    const float* keys   = (const float*)d_in[1];
    const float* query  = (const float*)d_in[2];
    const float* Wv     = (const float*)d_in[3];
    const float* Wk     = (const float*)d_in[4];
    const float* Wq     = (const float*)d_in[5];
    const float* Wo     = (const float*)d_in[6];
    const float* bo     = (const float*)d_in[7];

    attn_kernel<<<BN * TT * HH, 256>>>(values, keys, query, Wv, Wk, Wq);
    proj_kernel<<<BN * NN * TT / PRPB, 256>>>(Wo, bo, (float*)d_out);
}